// round 2
// baseline (speedup 1.0000x reference)
#include <cuda_runtime.h>

// Problem constants
constexpr int B_ = 16, C_ = 128, H_ = 72, W_ = 200, K_ = 9;
constexpr int CS = H_ * W_;               // channel stride (same in transposed layout)
constexpr size_t BS = (size_t)C_ * CS;    // batch stride
constexpr size_t TOTAL = (size_t)B_ * BS;

constexpr int TCO = 16;                   // c_out channels per CTA
constexpr int NCTA = C_ / TCO;            // 8 CTAs per cluster (one batch image)
constexpr int WSZ = C_ * K_;              // 1152 weights per c_out
constexpr int NTHR = 512;

// Scratch for the (B,C,W,H)-transposed layout
__device__ float g_tbuf[TOTAL];

// Persistent pass kernel: runs forward scan with wA then backward scan with wB.
// Cluster of 8 CTAs covers one batch image; CTA 'slice' owns c_out [slice*16,(slice+1)*16).
// L = conv-axis length (contiguous), nrows = scan-axis length.
template <int L, int JT>
__global__ void __launch_bounds__(NTHR, 1) __cluster_dims__(NCTA, 1, 1)
pass_kernel(float* __restrict__ base, const float* __restrict__ wA,
            const float* __restrict__ wB, int nrows) {
    constexpr int NJG = L / JT;                 // j-groups (exact for 200/4, 72/2)
    constexpr int PSTR = ((L + 8 + 3) / 4) * 4; // padded prev-row stride (16B mult)

    extern __shared__ float sm[];
    float* w_s = sm;                 // [1152][16]  (r = ci*9+k major, co minor)
    float* p_s = sm + WSZ * TCO;     // [128][PSTR] prev row, halo of 4 each side

    const int t = threadIdx.x;
    const int slice = blockIdx.x;    // 0..7
    const int b = blockIdx.y;
    const int coBase = slice * TCO;
    float* __restrict__ bb = base + (size_t)b * BS;

    const int cog = t & 7;           // co pair group (8)
    const int jg = t >> 3;           // j group
    const bool active = (jg < NJG);

    // zero p_s once (halo stays zero; interior rewritten each step)
    for (int i = t; i < C_ * PSTR; i += NTHR) p_s[i] = 0.f;

    for (int dir = 0; dir < 2; ++dir) {
        const float* __restrict__ w = dir ? wB : wA;
        __syncthreads();
        // stage this CTA's weight slice once per direction
        for (int i = t; i < WSZ * TCO; i += NTHR) {
            int co = i / WSZ;
            int r = i % WSZ;
            w_s[r * TCO + co] = w[(size_t)(coBase + co) * WSZ + r];
        }
        __syncthreads();

        for (int s = 1; s < nrows; ++s) {
            const int cur = dir ? (nrows - 1 - s) : s;
            const int prev = dir ? (cur + 1) : (cur - 1);
            const float* __restrict__ prow = bb + (size_t)prev * L;
            float* __restrict__ crow = bb + (size_t)cur * L;

            // cooperative load: full prev row (all 128 ci) into p_s interior
            #pragma unroll 4
            for (int i = t; i < C_ * (L / 4); i += NTHR) {
                int ci = i / (L / 4);
                int q = i % (L / 4);
                *(float4*)&p_s[ci * PSTR + 4 + q * 4] =
                    *(const float4*)&prow[(size_t)ci * CS + q * 4];
            }
            __syncthreads();

            if (active) {
                float acc0[JT], acc1[JT];
                #pragma unroll
                for (int n = 0; n < JT; ++n) { acc0[n] = 0.f; acc1[n] = 0.f; }

                const float* pr = p_s + jg * JT;
                const float* wr = w_s + cog * 2;

                #pragma unroll 2
                for (int ci = 0; ci < C_; ++ci) {
                    float pw[JT + 8];
                    if constexpr (JT == 4) {
                        float4 a = *(const float4*)(pr);
                        float4 c = *(const float4*)(pr + 4);
                        float4 d = *(const float4*)(pr + 8);
                        pw[0]=a.x; pw[1]=a.y; pw[2]=a.z; pw[3]=a.w;
                        pw[4]=c.x; pw[5]=c.y; pw[6]=c.z; pw[7]=c.w;
                        pw[8]=d.x; pw[9]=d.y; pw[10]=d.z; pw[11]=d.w;
                    } else {
                        #pragma unroll
                        for (int q = 0; q < (JT + 8) / 2; ++q) {
                            float2 v = *(const float2*)(pr + 2 * q);
                            pw[2*q] = v.x; pw[2*q+1] = v.y;
                        }
                    }
                    #pragma unroll
                    for (int k = 0; k < K_; ++k) {
                        float2 wv = *(const float2*)(wr + (ci * K_ + k) * TCO);
                        #pragma unroll
                        for (int n = 0; n < JT; ++n) {
                            acc0[n] = fmaf(wv.x, pw[k + n], acc0[n]);
                            acc1[n] = fmaf(wv.y, pw[k + n], acc1[n]);
                        }
                    }
                    pr += PSTR;
                }

                // cur += relu(acc)  (each (co,j) owned by exactly one thread chip-wide)
                const size_t o0 = (size_t)(coBase + cog * 2) * CS;
                #pragma unroll
                for (int n = 0; n < JT; ++n) {
                    int j = jg * JT + n;
                    crow[o0 + j]      += fmaxf(acc0[n], 0.f);
                    crow[o0 + CS + j] += fmaxf(acc1[n], 0.f);
                }
            }

            // cluster-wide barrier: release our global writes, acquire peers'
            asm volatile("barrier.cluster.arrive.aligned;" ::: "memory");
            asm volatile("barrier.cluster.wait.aligned;" ::: "memory");
        }
    }
}

// Transpose per (b,c) slab: src slab R x Cc (row-major) -> dst slab Cc x R.
__global__ void transpose_kernel(const float* __restrict__ src, float* __restrict__ dst,
                                 int R, int Cc) {
    __shared__ float tile[32][33];
    const size_t slab = blockIdx.z;
    const float* s = src + slab * (size_t)(R * Cc);
    float* d = dst + slab * (size_t)(R * Cc);
    const int c0 = blockIdx.x * 32;
    const int r0 = blockIdx.y * 32;

    #pragma unroll
    for (int i = 0; i < 32; i += 8) {
        int r = r0 + threadIdx.y + i;
        int c = c0 + threadIdx.x;
        if (r < R && c < Cc) tile[threadIdx.y + i][threadIdx.x] = s[(size_t)r * Cc + c];
    }
    __syncthreads();
    #pragma unroll
    for (int i = 0; i < 32; i += 8) {
        int c = c0 + threadIdx.y + i;
        int r = r0 + threadIdx.x;
        if (r < R && c < Cc) d[(size_t)c * R + r] = tile[threadIdx.x][threadIdx.y + i];
    }
}

extern "C" void kernel_launch(void* const* d_in, const int* in_sizes, int n_in,
                              void* d_out, int out_size) {
    const float* x  = (const float*)d_in[0];
    const float* wd = (const float*)d_in[1];
    const float* wu = (const float*)d_in[2];
    const float* wr = (const float*)d_in[3];
    const float* wl = (const float*)d_in[4];
    float* out = (float*)d_out;

    float* tbuf = nullptr;
    cudaGetSymbolAddress((void**)&tbuf, g_tbuf);

    constexpr int SMEM_W = (WSZ * TCO + C_ * 208) * 4;  // 180,224 B
    constexpr int SMEM_H = (WSZ * TCO + C_ * 80) * 4;   // 114,688 B
    static bool attr_done = false;
    if (!attr_done) {
        cudaFuncSetAttribute(pass_kernel<W_, 4>,
                             cudaFuncAttributeMaxDynamicSharedMemorySize, SMEM_W);
        cudaFuncSetAttribute(pass_kernel<H_, 2>,
                             cudaFuncAttributeMaxDynamicSharedMemorySize, SMEM_H);
        attr_done = true;
    }

    // working copy of x (scan runs in-place)
    cudaMemcpyAsync(out, x, TOTAL * sizeof(float), cudaMemcpyDeviceToDevice);

    const dim3 grid(NCTA, B_, 1);

    // down + up: conv along W (contiguous), scan over H rows
    pass_kernel<W_, 4><<<grid, NTHR, SMEM_W>>>(out, wd, wu, H_);

    // transpose (B,C,H,W) -> (B,C,W,H)
    const dim3 tb(32, 8);
    const dim3 tg1((W_ + 31) / 32, (H_ + 31) / 32, B_ * C_);
    transpose_kernel<<<tg1, tb>>>(out, tbuf, H_, W_);

    // right + left: conv along H (now contiguous), scan over W rows
    pass_kernel<H_, 2><<<grid, NTHR, SMEM_H>>>(tbuf, wr, wl, W_);

    // transpose back
    const dim3 tg2((H_ + 31) / 32, (W_ + 31) / 32, B_ * C_);
    transpose_kernel<<<tg2, tb>>>(tbuf, out, W_, H_);
}